// round 17
// baseline (speedup 1.0000x reference)
#include <cuda_runtime.h>
#include <cstdint>

// EquiLocalPatOrientConvolution: B=2, I=32, O=64, D=H=W=48, K=5 (pad 2).
// v17 = v16 (256 thr, 8x8x4 tile, quad packing, conflict-free LDS.128 radial,
// permuted Ys float2 A-loads) with the tf32 2-split moved to B (pre-split in
// prep kernel): A hi-only -> -80 ALU ops/warp-quad in gemm. rel_err ~2e-4.

#define DIMS  48
#define TX    8
#define TY    8
#define TZ    4
#define HX    12
#define HY    12
#define HZ    8
#define NI    32
#define NO    64
#define NP    10
#define Y0C   0.28209479177387814f
#define NTHR  256
#define NQUAD 8
#define NKS   5                          // k8 steps per quad (K=40)

#define XS_CELLS   (HZ * HY * HX)        // 1152 float4 cells per buffer
#define YS_STRIDE  264                   // 256 vox + 8 pad
#define YS_FLOATS  (40 * YS_STRIDE)      // 10560
#define SMEM_FLOATS (2 * 4 * XS_CELLS + YS_FLOATS)  // 9216 + 10560
#define SMEM_BYTES  (SMEM_FLOATS * 4 + 256)         // ~79.4 KB -> 2 blocks/SM

typedef unsigned long long ull_t;

__device__ __host__ constexpr int p_of_r2(int r2) {
    return r2 <= 6 ? r2 : (r2 == 8 ? 7 : (r2 == 9 ? 8 : 9));
}

// B fragments: [quad][ks][nt][lane] -> float4 {b0hi, b1hi, b0lo, b1lo}
__device__ float4 g_Bf[NQUAD * NKS * 8 * 32];

__device__ __forceinline__ uint32_t tf32_rna(float x) {
    uint32_t r;
    asm("cvt.rna.tf32.f32 %0, %1;" : "=r"(r) : "f"(x));
    return r;
}

__device__ __forceinline__ void mma_tf32(float* c,
                                         uint32_t a0, uint32_t a1, uint32_t a2, uint32_t a3,
                                         uint32_t b0, uint32_t b1) {
    asm("mma.sync.aligned.m16n8k8.row.col.f32.tf32.tf32.f32 "
        "{%0,%1,%2,%3}, {%4,%5,%6,%7}, {%8,%9}, {%0,%1,%2,%3};"
        : "+f"(c[0]), "+f"(c[1]), "+f"(c[2]), "+f"(c[3])
        : "r"(a0), "r"(a1), "r"(a2), "r"(a3), "r"(b0), "r"(b1));
}

// ---------- prep: W[o][ci][p] -> B-fragment layout, Y0 folded, hi/lo tf32 ----------
__global__ void bprep_kernel(const float* __restrict__ wg) {
    int idx = blockIdx.x * 256 + threadIdx.x;
    if (idx >= NQUAD * NKS * 8 * 32) return;
    int lane = idx & 31;
    int r    = idx >> 5;
    int nt   = r & 7;  r >>= 3;
    int ks   = r % NKS;
    int quad = r / NKS;
    int gid = lane >> 2, tidg = lane & 3;
    int o = nt * 8 + gid;
    auto getw = [&](int k) -> float {        // k in 0..39
        int ci = quad * 4 + k / 10;
        int p  = k % 10;
        return Y0C * wg[o * (NI * NP) + ci * NP + p];
    };
    float b0 = getw(ks * 8 + tidg);
    float b1 = getw(ks * 8 + tidg + 4);
    uint32_t b0h = tf32_rna(b0), b1h = tf32_rna(b1);
    uint32_t b0l = tf32_rna(b0 - __uint_as_float(b0h));
    uint32_t b1l = tf32_rna(b1 - __uint_as_float(b1h));
    g_Bf[idx] = make_float4(__uint_as_float(b0h), __uint_as_float(b1h),
                            __uint_as_float(b0l), __uint_as_float(b1l));
}

// ---------- main ----------
__global__ void __launch_bounds__(NTHR, 2)
econv_kernel(const float* __restrict__ x,
             const float* __restrict__ bias,
             float* __restrict__ out)
{
    extern __shared__ float smem[];
    float4* xs[2];
    xs[0] = (float4*)smem;
    xs[1] = xs[0] + XS_CELLS;
    float* Ys = smem + 8 * XS_CELLS;            // [k][perm(vox)], stride 264

    const int tid  = threadIdx.x;
    const int wid  = tid >> 5;                  // 0..7
    const int lid  = tid & 31;
    const int gid  = lid >> 2;
    const int tidg = lid & 3;
    const int b    = blockIdx.y;
    const int t    = blockIdx.x;                // 6x6x12
    const int tz   = t / 36;
    const int ty   = (t % 36) / 6;
    const int tx   = t % 6;
    const int z0   = tz * TZ, y0 = ty * TY, x0 = tx * TX;

    const size_t x_chan = (size_t)DIMS * DIMS * DIMS;
    const float* xb = x + (size_t)b * NI * x_chan;

    float acc[64];
    #pragma unroll
    for (int k = 0; k < 64; k++) acc[k] = 0.0f;

    // ---- halo prefetch + commit for a quad (4 channels), coalesced ----
    auto load_quad = [&](int quad, float4* dst) {
        const float* c0 = xb + (size_t)(4 * quad) * x_chan;
        float4 pre[5];
        #pragma unroll
        for (int k = 0; k < 5; k++) {
            int idx = tid + k * NTHR;
            float4 v = make_float4(0.f, 0.f, 0.f, 0.f);
            if (idx < XS_CELLS) {
                int zz = idx / (HX * HY);
                int rr = idx % (HX * HY);
                int yy = rr / HX, xx = rr % HX;
                int gz = z0 + zz - 2, gy = y0 + yy - 2, gx = x0 + xx - 2;
                if ((unsigned)gz < (unsigned)DIMS &&
                    (unsigned)gy < (unsigned)DIMS &&
                    (unsigned)gx < (unsigned)DIMS) {
                    size_t off = ((size_t)gz * DIMS + gy) * DIMS + gx;
                    v.x = __ldg(&c0[off]);
                    v.y = __ldg(&c0[off + x_chan]);
                    v.z = __ldg(&c0[off + 2 * x_chan]);
                    v.w = __ldg(&c0[off + 3 * x_chan]);
                }
            }
            pre[k] = v;
        }
        #pragma unroll
        for (int k = 0; k < 5; k++) {
            int idx = tid + k * NTHR;
            if (idx < XS_CELLS) dst[idx] = pre[k];   // STS.128
        }
    };

    // Ys permutation: vox = base16 + 8s + g  ->  base16 + 2g + s
    const int pv = (tid & ~15) | ((tid & 7) << 1) | ((tid >> 3) & 1);

    // ---- radial: 1 voxel x 4 channels, 125 LDS.128, conflict-free ----
    auto radial = [&](const float4* xsrc) {
        const int vz = tid >> 6, vy = (tid >> 3) & 7, vx = tid & 7;
        ull_t y01[NP], y23[NP];
        #pragma unroll
        for (int p = 0; p < NP; p++) { y01[p] = 0ULL; y23[p] = 0ULL; }
        #pragma unroll
        for (int dz = 0; dz < 5; dz++) {
            #pragma unroll
            for (int dy = 0; dy < 5; dy++) {
                const float4* row = &xsrc[((vz + dz) * HY + (vy + dy)) * HX + vx];
                #pragma unroll
                for (int dx = 0; dx < 5; dx++) {
                    const int p = p_of_r2((dz - 2) * (dz - 2) +
                                          (dy - 2) * (dy - 2) +
                                          (dx - 2) * (dx - 2));
                    union { float4 f; ull_t u[2]; } c;
                    c.f = row[dx];
                    asm("add.rn.f32x2 %0, %0, %1;" : "+l"(y01[p]) : "l"(c.u[0]));
                    asm("add.rn.f32x2 %0, %0, %1;" : "+l"(y23[p]) : "l"(c.u[1]));
                }
            }
        }
        #pragma unroll
        for (int p = 0; p < NP; p++) {
            float2 a = *(float2*)&y01[p];
            float2 d = *(float2*)&y23[p];
            Ys[p * YS_STRIDE + pv]        = a.x;   // ch0 -> k rows 0..9
            Ys[(p + 10) * YS_STRIDE + pv] = a.y;   // ch1 -> k rows 10..19
            Ys[(p + 20) * YS_STRIDE + pv] = d.x;   // ch2 -> k rows 20..29
            Ys[(p + 30) * YS_STRIDE + pv] = d.y;   // ch3 -> k rows 30..39
        }
    };

    // ---- GEMM: A hi-only, B 2-split; warp = 32 vox x 64 out, K=40 ----
    auto gemm = [&](int quad) {
        const float4* bsrc = g_Bf + quad * (NKS * 8 * 32);
        #pragma unroll
        for (int ks = 0; ks < NKS; ks++) {
            uint32_t Ah[2][4];
            #pragma unroll
            for (int mt = 0; mt < 2; mt++) {
                const int base = wid * 32 + mt * 16 + 2 * gid;
                const float* yk = Ys + (ks * 8 + tidg) * YS_STRIDE;
                float2 a01 = *(const float2*)&yk[base];                  // rows g, g+8
                float2 a23 = *(const float2*)&yk[4 * YS_STRIDE + base];  // k+4
                Ah[mt][0] = tf32_rna(a01.x);
                Ah[mt][1] = tf32_rna(a01.y);
                Ah[mt][2] = tf32_rna(a23.x);
                Ah[mt][3] = tf32_rna(a23.y);
            }
            #pragma unroll
            for (int nt = 0; nt < 8; nt++) {
                float4 bf = __ldg(&bsrc[(ks * 8 + nt) * 32 + lid]);
                uint32_t b0h = __float_as_uint(bf.x);
                uint32_t b1h = __float_as_uint(bf.y);
                uint32_t b0l = __float_as_uint(bf.z);
                uint32_t b1l = __float_as_uint(bf.w);
                #pragma unroll
                for (int mt = 0; mt < 2; mt++) {
                    float* c = &acc[(mt * 8 + nt) * 4];
                    mma_tf32(c, Ah[mt][0], Ah[mt][1], Ah[mt][2], Ah[mt][3], b0h, b1h);
                    mma_tf32(c, Ah[mt][0], Ah[mt][1], Ah[mt][2], Ah[mt][3], b0l, b1l);
                }
            }
        }
    };

    // ---- prologue ----
    load_quad(0, xs[0]);
    __syncthreads();                 // xs(0) visible
    radial(xs[0]);                   // Ys(0)

    // ---- main loop over 8 quads (2 bars/iter, phase-pure regions) ----
    #pragma unroll 1
    for (int q = 0; q < NQUAD; q++) {
        __syncthreads();             // Ys(q) visible
        gemm(q);
        if (q + 1 < NQUAD) {
            load_quad(q + 1, xs[(q + 1) & 1]);
            __syncthreads();         // xs(q+1) visible; gemm done with Ys
            radial(xs[(q + 1) & 1]); // Ys(q+1)
        }
    }

    // ---- epilogue: stage through smem (aliases Ys) for coalesced stores ----
    __syncthreads();
    float* stage = Ys;               // [c16][vox 0..255], stride YS_STRIDE
    #pragma unroll 1
    for (int chunk = 0; chunk < 4; chunk++) {
        if (chunk) __syncthreads();
        #pragma unroll
        for (int mt = 0; mt < 2; mt++) {
            #pragma unroll
            for (int nt2 = 0; nt2 < 2; nt2++) {
                const int nt = chunk * 2 + nt2;
                #pragma unroll
                for (int r = 0; r < 4; r++) {
                    int vox = wid * 32 + mt * 16 + gid + ((r >> 1) << 3);
                    int c16 = nt2 * 8 + 2 * tidg + (r & 1);
                    stage[c16 * YS_STRIDE + vox] = acc[(mt * 8 + nt) * 4 + r];
                }
            }
        }
        __syncthreads();
        // 4 rounds x 256 threads: one float4 each
        #pragma unroll
        for (int round = 0; round < 4; round++) {
            const int idx = round * 256 + tid;
            const int o16 = idx >> 6;            // 0..15
            const int q4  = idx & 63;            // float4 group over 256 vox
            const int o   = chunk * 16 + o16;
            const float bb = __ldg(&bias[o]);
            float4 v = *(float4*)&stage[o16 * YS_STRIDE + q4 * 4];
            v.x += bb; v.y += bb; v.z += bb; v.w += bb;
            const int gz = z0 + (q4 >> 4);
            const int gy = y0 + ((q4 >> 1) & 7);
            const int gx = x0 + (q4 & 1) * 4;
            float* dst = out + ((size_t)b * NO + o) * x_chan
                             + ((size_t)gz * DIMS + gy) * DIMS + gx;
            *(float4*)dst = v;
        }
    }
}

extern "C" void kernel_launch(void* const* d_in, const int* in_sizes, int n_in,
                              void* d_out, int out_size)
{
    const float* x    = (const float*)d_in[0];   // [2,32,1,48,48,48]
    const float* w    = (const float*)d_in[1];   // [64,32,1,1,1,10]
    const float* bias = (const float*)d_in[2];   // [64]
    float* out = (float*)d_out;                  // [2,64,1,48,48,48]

    bprep_kernel<<<(NQUAD * NKS * 8 * 32 + 255) / 256, 256>>>(w);

    cudaFuncSetAttribute(econv_kernel,
                         cudaFuncAttributeMaxDynamicSharedMemorySize, SMEM_BYTES);
    dim3 grid(432, 2);   // 6x6x12 spatial tiles x batch
    econv_kernel<<<grid, NTHR, SMEM_BYTES>>>(x, bias, out);
}